// round 9
// baseline (speedup 1.0000x reference)
#include <cuda_runtime.h>

// ---------------------------------------------------------------------------
// GAT (2 layers, edge features, H=2 heads x C=16) + mean pool + MLP -> [G,2]
// dst-CSR built once; atomic-free warp-per-node aggregation, 2 edges per
// iteration (half-warp each, float2 columns), software-pipelined prefetch of
// the next edge batch; layer-2 transform fused into agg0 epilogue; pool fused
// into agg1.
// ---------------------------------------------------------------------------

#define MAXN 100352
#define MAXE 3211264
#define MAXG 256
#define NBS ((MAXN + 1023) / 1024)

__device__ __align__(16) float g_h[MAXN * 32];      // layer-1 transformed features
__device__ __align__(16) float g_out[MAXN * 32];    // layer-2 transformed features
__device__ __align__(16) float g_asrc[MAXN * 2];
__device__ __align__(16) float g_adst[MAXN * 2];
__device__ __align__(16) float g_asrc2[MAXN * 2];
__device__ __align__(16) float g_adst2[MAXN * 2];
__device__ __align__(16) int2  g_csr[MAXE];         // (src, ea_bits), dst-sorted
__device__ int g_rank[MAXE];
__device__ int g_rowptr[MAXN + 1];
__device__ int g_deg[MAXN];
__device__ int g_bsum[NBS];
__device__ int g_boff[NBS];
__device__ __align__(16) float g_scal[8];           // [0]=esum [1]=mean [2..5]=ce
__device__ __align__(16) float g_pool[MAXG * 32];
__device__ float g_cnt[MAXG];

__device__ __forceinline__ int clampi(int v, int hi) {
    return v < 0 ? 0 : (v >= hi ? hi - 1 : v);
}

// ---------------------------------------------------------------------------
__global__ void k_init(int n) {
    int stride = gridDim.x * blockDim.x;
    for (int i = blockIdx.x * blockDim.x + threadIdx.x; i < n; i += stride)
        g_deg[i] = 0;
    int t = blockIdx.x * blockDim.x + threadIdx.x;
    if (t < 8) g_scal[t] = 0.f;
    if (t < MAXG) g_cnt[t] = 0.f;
    if (t < MAXG * 32) g_pool[t] = 0.f;
}

// histogram (captures per-edge rank) + edge_attr sum in one pass
__global__ void k_hist(const int* __restrict__ ei, const float* __restrict__ ea,
                       int E, int n) {
    __shared__ float red[256];
    float acc = 0.f;
    for (int e = blockIdx.x * 256 + threadIdx.x; e < E; e += gridDim.x * 256) {
        int d = clampi(ei[E + e], n);
        g_rank[e] = atomicAdd(&g_deg[d], 1);
        acc += ea[e];
    }
    red[threadIdx.x] = acc;
    __syncthreads();
    for (int s = 128; s; s >>= 1) {
        if (threadIdx.x < s) red[threadIdx.x] += red[threadIdx.x + s];
        __syncthreads();
    }
    if (threadIdx.x == 0) atomicAdd(&g_scal[0], red[0]);
}

__global__ void k_prep(const float* __restrict__ We1, const float* __restrict__ ae1,
                       const float* __restrict__ We2, const float* __restrict__ ae2, int E) {
    int t = threadIdx.x;
    if (t == 0) g_scal[1] = g_scal[0] / (float)E;
    if (t < 4) {
        int layer = t >> 1, hh = t & 1;
        const float* We = layer ? We2 : We1;
        const float* ae = layer ? ae2 : ae1;
        float c = 0.f;
        for (int i = 0; i < 16; i++) c += We[hh * 16 + i] * ae[hh * 16 + i];
        g_scal[2 + layer * 2 + hh] = c;
    }
}

// ---------------------------------------------------------------------------
__global__ void k_scan1(int n) {
    __shared__ int sm[1024];
    int t = threadIdx.x;
    int i = blockIdx.x * 1024 + t;
    int v = (i < n) ? g_deg[i] : 0;
    int x = v;
    sm[t] = x;
    __syncthreads();
    #pragma unroll
    for (int off = 1; off < 1024; off <<= 1) {
        int y = (t >= off) ? sm[t - off] : 0;
        __syncthreads();
        x += y;
        sm[t] = x;
        __syncthreads();
    }
    if (i < n) g_rowptr[i] = x - v;   // exclusive, pre-offset
    if (t == 1023) g_bsum[blockIdx.x] = x;
}

__global__ void k_scan2(int nb) {
    __shared__ int sm[1024];
    int t = threadIdx.x;
    int v = (t < nb) ? g_bsum[t] : 0;
    int x = v;
    sm[t] = x;
    __syncthreads();
    #pragma unroll
    for (int off = 1; off < 1024; off <<= 1) {
        int y = (t >= off) ? sm[t - off] : 0;
        __syncthreads();
        x += y;
        sm[t] = x;
        __syncthreads();
    }
    if (t < nb) g_boff[t] = x - v;    // exclusive
}

__global__ void k_scan3(int n, int E) {
    int i = blockIdx.x * blockDim.x + threadIdx.x;
    if (i < n)
        g_rowptr[i] += g_boff[i >> 10];
    if (i == 0) g_rowptr[n] = E;
}

// atomic-free scatter: slot = rowptr[dst] + rank[e]
__global__ void k_scatter(const int* __restrict__ ei, const float* __restrict__ ea,
                          int E, int n) {
    for (int e = blockIdx.x * blockDim.x + threadIdx.x; e < E; e += gridDim.x * blockDim.x) {
        int s = clampi(ei[e], n);
        int d = clampi(ei[E + e], n);
        g_csr[g_rowptr[d] + g_rank[e]] = make_int2(s, __float_as_int(ea[e]));
    }
}

// ---------------------------------------------------------------------------
// layer-1 transform: h = x @ W1; emits asrc/adst.
__global__ void k_transform1(const float* __restrict__ xin,
                             const float* __restrict__ W,
                             const float* __restrict__ a_src,
                             const float* __restrict__ a_dst, int n) {
    constexpr int FIN = 128;
    __shared__ float W_sh[FIN * 32];
    __shared__ float x_sh[32][FIN + 1];
    __shared__ float s_as[32], s_ad[32];
    __shared__ float sm_ps[8][32], sm_pd[8][32];
    int tid = threadIdx.x;
    for (int i = tid; i < FIN * 32; i += 256) W_sh[i] = W[i];
    if (tid < 32) {
        s_as[tid] = a_src[tid];
        s_ad[tid] = a_dst[tid];
    }
    __syncthreads();
    int nb = blockIdx.x * 32;
    for (int i = tid; i < 32 * FIN; i += 256) {
        int r = i / FIN, c = i % FIN;
        int node = nb + r;
        x_sh[r][c] = (node < n) ? xin[(size_t)node * FIN + c] : 0.f;
    }
    __syncthreads();

    int w = tid >> 5, lane = tid & 31;
    int node = nb + lane;
    float4 acc = make_float4(0.f, 0.f, 0.f, 0.f);
    const float4* W4 = (const float4*)W_sh;
    #pragma unroll 8
    for (int k = 0; k < FIN; k++) {
        float4 wv = W4[k * 8 + w];     // same addr across warp -> broadcast
        float xv = x_sh[lane][k];      // conflict-free (stride FIN+1)
        acc.x = fmaf(xv, wv.x, acc.x);
        acc.y = fmaf(xv, wv.y, acc.y);
        acc.z = fmaf(xv, wv.z, acc.z);
        acc.w = fmaf(xv, wv.w, acc.w);
    }
    if (node < n)
        ((float4*)(g_h + node * 32))[w] = acc;

    sm_ps[w][lane] = acc.x * s_as[w * 4]     + acc.y * s_as[w * 4 + 1]
                   + acc.z * s_as[w * 4 + 2] + acc.w * s_as[w * 4 + 3];
    sm_pd[w][lane] = acc.x * s_ad[w * 4]     + acc.y * s_ad[w * 4 + 1]
                   + acc.z * s_ad[w * 4 + 2] + acc.w * s_ad[w * 4 + 3];
    __syncthreads();
    if (tid < 64) {
        int l = tid & 31, hh = tid >> 5;
        int node2 = nb + l;
        if (node2 < n) {
            int wb = hh * 4;
            float vs = sm_ps[wb][l] + sm_ps[wb + 1][l] + sm_ps[wb + 2][l] + sm_ps[wb + 3][l];
            float vd = sm_pd[wb][l] + sm_pd[wb + 1][l] + sm_pd[wb + 2][l] + sm_pd[wb + 3][l];
            g_asrc[node2 * 2 + hh] = vs;
            g_adst[node2 * 2 + hh] = vd;
        }
    }
}

// ---------------------------------------------------------------------------
// fused aggregation: warp per dst node; 2 edges per gather iteration
// (half-warp each, float2 column pairs); next batch's csr + asrc prefetched
// into registers before the gather loop so their latency overlaps it.
// LAYER==0: features g_h/asrc/adst; epilogue = layer-2 transform -> g_out.
// LAYER==1: features g_out/asrc2/adst2; epilogue = mean-pool accumulation.
template <int LAYER>
__global__ void __launch_bounds__(256, 6)
k_agg(int n,
      const float* __restrict__ W2, const float* __restrict__ b1,
      const float* __restrict__ as2, const float* __restrict__ ad2,
      const int* __restrict__ batch, const float* __restrict__ b2,
      int G) {
    __shared__ float4 stage[8][32];
    __shared__ float W2s[32 * 32];
    __shared__ float b1s[32], as2s[32], ad2s[32];
    int tid = threadIdx.x;
    if (LAYER == 0) {
        for (int i = tid; i < 1024; i += 256) W2s[i] = W2[i];
        if (tid < 32) {
            b1s[tid] = b1[tid];
            as2s[tid] = as2[tid];
            ad2s[tid] = ad2[tid];
        }
        __syncthreads();
    }

    int wg = (blockIdx.x * blockDim.x + tid) >> 5;
    if (wg >= n) return;
    int w = tid >> 5, lane = tid & 31;
    int hl = lane & 15;            // half-warp lane -> column pair (2*hl, 2*hl+1)
    int half = lane >> 4;          // 0: even edge slot, 1: odd edge slot
    int node = wg;
    float c0 = g_scal[2 + LAYER * 2];
    float c1 = g_scal[3 + LAYER * 2];
    float mean = g_scal[1];
    const float*  hf   = LAYER ? g_out   : g_h;
    const float2* hf2  = (const float2*)hf;
    const float*  asrc = LAYER ? g_asrc2 : g_asrc;
    const float*  adst = LAYER ? g_adst2 : g_adst;
    float2 ad = ((const float2*)adst)[node];
    bool head1 = hl >= 8;          // which head this column pair belongs to

    float2 acc = make_float2(0.f, 0.f);
    float s0 = 0.f, s1 = 0.f;
    int beg = g_rowptr[node], end = g_rowptr[node + 1];

    // ---- prefetch batch 0 ----
    int jj = beg + lane;
    bool cv = jj < end;
    int2 cp = cv ? g_csr[jj] : make_int2(node, 0);
    float2 cas = ((const float2*)asrc)[cp.x];

    for (int j0 = beg; j0 < end; j0 += 32) {
        // alpha/ex from prefetched regs
        float av = __int_as_float(cp.y);
        float a0 = cas.x + ad.x + av * c0;
        float a1 = cas.y + ad.y + av * c1;
        a0 = a0 > 0.f ? a0 : 0.2f * a0;
        a1 = a1 > 0.f ? a1 : 0.2f * a1;
        float ex0 = cv ? __expf(a0) : 0.f;   // invalid lanes stage ex=0
        float ex1 = cv ? __expf(a1) : 0.f;
        s0 += ex0;
        s1 += ex1;
        stage[w][lane] = make_float4(__int_as_float(cp.x), ex0, ex1, 0.f);

        // ---- prefetch batch k+1 (latency overlaps the gather loop below) ----
        int jn = j0 + 32 + lane;
        cv = jn < end;
        cp = cv ? g_csr[jn] : make_int2(node, 0);
        cas = ((const float2*)asrc)[cp.x];

        __syncwarp();
        int cnt = min(end - j0, 32);
        if (cnt == 32) {
            #pragma unroll
            for (int t = 0; t < 32; t += 2) {
                float4 p = stage[w][t + half];            // broadcast LDS.128 x2
                float2 hv = hf2[__float_as_int(p.x) * 16 + hl];
                float e = head1 ? p.z : p.y;
                acc.x = fmaf(hv.x, e, acc.x);
                acc.y = fmaf(hv.y, e, acc.y);
            }
        } else {
            for (int t = 0; t < cnt; t += 2) {
                float4 p = stage[w][t + half];            // slot >= cnt has ex=0
                float2 hv = hf2[__float_as_int(p.x) * 16 + hl];
                float e = head1 ? p.z : p.y;
                acc.x = fmaf(hv.x, e, acc.x);
                acc.y = fmaf(hv.y, e, acc.y);
            }
        }
        __syncwarp();
    }

    // self loop (src = node, ea = mean) -- applied by lanes 0-15 only
    {
        float2 as = ((const float2*)asrc)[node];
        float a0 = as.x + ad.x + mean * c0;
        float a1 = as.y + ad.y + mean * c1;
        a0 = a0 > 0.f ? a0 : 0.2f * a0;
        a1 = a1 > 0.f ? a1 : 0.2f * a1;
        float ex0 = __expf(a0), ex1 = __expf(a1);
        if (lane == 0) { s0 += ex0; s1 += ex1; }
        float2 hv = hf2[node * 16 + hl];
        float e = (lane < 16) ? (head1 ? ex1 : ex0) : 0.f;
        acc.x = fmaf(hv.x, e, acc.x);
        acc.y = fmaf(hv.y, e, acc.y);
    }

    // combine half-warps (both halves hold the same column pairs)
    acc.x += __shfl_down_sync(0xffffffffu, acc.x, 16);
    acc.y += __shfl_down_sync(0xffffffffu, acc.y, 16);

    #pragma unroll
    for (int off = 16; off; off >>= 1) {
        s0 += __shfl_xor_sync(0xffffffffu, s0, off);
        s1 += __shfl_xor_sync(0xffffffffu, s1, off);
    }
    float sinv = 1.f / ((head1 ? s1 : s0) + 1e-16f);
    float2 o2 = make_float2(acc.x * sinv, acc.y * sinv);   // valid in lanes 0-15

    if (LAYER == 0) {
        // fused layer-2 transform: x2 = relu(o + b1); h2 = x2 @ W2
        float* xrow = (float*)&stage[w][0];
        if (lane < 16) {
            xrow[2 * hl]     = fmaxf(o2.x + b1s[2 * hl], 0.f);
            xrow[2 * hl + 1] = fmaxf(o2.y + b1s[2 * hl + 1], 0.f);
        }
        __syncwarp();
        float acc2 = 0.f;
        #pragma unroll 8
        for (int k = 0; k < 32; k++)
            acc2 = fmaf(xrow[k], W2s[k * 32 + lane], acc2);
        g_out[node * 32 + lane] = acc2;
        float ps = acc2 * as2s[lane];
        float pd = acc2 * ad2s[lane];
        #pragma unroll
        for (int off = 8; off; off >>= 1) {
            ps += __shfl_down_sync(0xffffffffu, ps, off, 16);
            pd += __shfl_down_sync(0xffffffffu, pd, off, 16);
        }
        if ((lane & 15) == 0) {
            int hh = lane >> 4;
            g_asrc2[node * 2 + hh] = ps;
            g_adst2[node * 2 + hh] = pd;
        }
    } else {
        int g = clampi(batch[node], G);
        if (lane < 16) {
            float2 add = make_float2(o2.x + b2[2 * hl], o2.y + b2[2 * hl + 1]);
            atomicAdd((float2*)&g_pool[g * 32 + 2 * hl], add);
        }
        if (lane == 0) atomicAdd(&g_cnt[g], 1.f);
    }
}

// ---------------------------------------------------------------------------
__global__ void k_mlp(float* __restrict__ out,
                      const float* __restrict__ Wf1, const float* __restrict__ bf1,
                      const float* __restrict__ Wf2, const float* __restrict__ bf2, int G) {
    int g = blockIdx.x * blockDim.x + threadIdx.x;
    if (g >= G) return;
    float inv = 1.f / fmaxf(g_cnt[g], 1.f);
    float emb[32];
    #pragma unroll
    for (int i = 0; i < 32; i++) emb[i] = g_pool[g * 32 + i] * inv;
    float o0 = bf2[0], o1 = bf2[1];
    for (int j = 0; j < 32; j++) {
        float z = bf1[j];
        #pragma unroll
        for (int i = 0; i < 32; i++) z = fmaf(emb[i], Wf1[i * 32 + j], z);
        z = fmaxf(z, 0.f);
        o0 = fmaf(z, Wf2[j * 2], o0);
        o1 = fmaf(z, Wf2[j * 2 + 1], o1);
    }
    out[g * 2] = o0;
    out[g * 2 + 1] = o1;
}

// ---------------------------------------------------------------------------
extern "C" void kernel_launch(void* const* d_in, const int* in_sizes, int n_in,
                              void* d_out, int out_size) {
    const float* x     = (const float*)d_in[0];
    const int*   ei    = (const int*)d_in[1];
    const float* ea    = (const float*)d_in[2];
    const int*   batch = (const int*)d_in[3];
    const float* W1  = (const float*)d_in[4];
    const float* as1 = (const float*)d_in[5];
    const float* ad1 = (const float*)d_in[6];
    const float* We1 = (const float*)d_in[7];
    const float* ae1 = (const float*)d_in[8];
    const float* b1  = (const float*)d_in[9];
    const float* W2  = (const float*)d_in[10];
    const float* as2 = (const float*)d_in[11];
    const float* ad2 = (const float*)d_in[12];
    const float* We2 = (const float*)d_in[13];
    const float* ae2 = (const float*)d_in[14];
    const float* b2  = (const float*)d_in[15];
    const float* Wf1 = (const float*)d_in[16];
    const float* bf1 = (const float*)d_in[17];
    const float* Wf2 = (const float*)d_in[18];
    const float* bf2 = (const float*)d_in[19];

    int N = in_sizes[0] / 128;
    int E = in_sizes[1] / 2;
    int G = out_size / 2;
    int nb = (N + 1023) / 1024;
    int tb = (N + 31) / 32;
    int ab = (N + 7) / 8;

    k_init<<<128, 1024>>>(N);
    k_hist<<<2048, 256>>>(ei, ea, E, N);
    k_prep<<<1, 32>>>(We1, ae1, We2, ae2, E);

    k_scan1<<<nb, 1024>>>(N);
    k_scan2<<<1, 1024>>>(nb);
    k_scan3<<<(N + 1023) / 1024, 1024>>>(N, E);
    k_scatter<<<2048, 512>>>(ei, ea, E, N);

    // layer 1 transform, then agg0 (with fused layer-2 transform epilogue)
    k_transform1<<<tb, 256>>>(x, W1, as1, ad1, N);
    k_agg<0><<<ab, 256>>>(N, W2, b1, as2, ad2, nullptr, nullptr, G);

    // layer 2 aggregation with fused mean-pool
    k_agg<1><<<ab, 256>>>(N, nullptr, nullptr, nullptr, nullptr, batch, b2, G);

    k_mlp<<<1, 64>>>((float*)d_out, Wf1, bf1, Wf2, bf2, G);
}

// round 10
// speedup vs baseline: 1.0567x; 1.0567x over previous
#include <cuda_runtime.h>

// ---------------------------------------------------------------------------
// GAT (2 layers, edge features, H=2 heads x C=16) + mean pool + MLP -> [G,2]
// dst-CSR built once; atomic-free warp-per-node aggregation, 4 edges per
// gather iteration (8-lane groups, float4 columns); layer-2 transform fused
// into agg0 epilogue; pool fused into agg1.
// ---------------------------------------------------------------------------

#define MAXN 100352
#define MAXE 3211264
#define MAXG 256
#define NBS ((MAXN + 1023) / 1024)

__device__ __align__(16) float g_h[MAXN * 32];      // layer-1 transformed features
__device__ __align__(16) float g_out[MAXN * 32];    // layer-2 transformed features
__device__ __align__(16) float g_asrc[MAXN * 2];
__device__ __align__(16) float g_adst[MAXN * 2];
__device__ __align__(16) float g_asrc2[MAXN * 2];
__device__ __align__(16) float g_adst2[MAXN * 2];
__device__ __align__(16) int2  g_csr[MAXE];         // (src, ea_bits), dst-sorted
__device__ int g_rank[MAXE];
__device__ int g_rowptr[MAXN + 1];
__device__ int g_deg[MAXN];
__device__ int g_bsum[NBS];
__device__ int g_boff[NBS];
__device__ __align__(16) float g_scal[8];           // [0]=esum [1]=mean [2..5]=ce
__device__ __align__(16) float g_pool[MAXG * 32];
__device__ float g_cnt[MAXG];

__device__ __forceinline__ int clampi(int v, int hi) {
    return v < 0 ? 0 : (v >= hi ? hi - 1 : v);
}

// ---------------------------------------------------------------------------
__global__ void k_init(int n) {
    int stride = gridDim.x * blockDim.x;
    for (int i = blockIdx.x * blockDim.x + threadIdx.x; i < n; i += stride)
        g_deg[i] = 0;
    int t = blockIdx.x * blockDim.x + threadIdx.x;
    if (t < 8) g_scal[t] = 0.f;
    if (t < MAXG) g_cnt[t] = 0.f;
    if (t < MAXG * 32) g_pool[t] = 0.f;
}

// histogram (captures per-edge rank) + edge_attr sum in one pass
__global__ void k_hist(const int* __restrict__ ei, const float* __restrict__ ea,
                       int E, int n) {
    __shared__ float red[256];
    float acc = 0.f;
    for (int e = blockIdx.x * 256 + threadIdx.x; e < E; e += gridDim.x * 256) {
        int d = clampi(ei[E + e], n);
        g_rank[e] = atomicAdd(&g_deg[d], 1);
        acc += ea[e];
    }
    red[threadIdx.x] = acc;
    __syncthreads();
    for (int s = 128; s; s >>= 1) {
        if (threadIdx.x < s) red[threadIdx.x] += red[threadIdx.x + s];
        __syncthreads();
    }
    if (threadIdx.x == 0) atomicAdd(&g_scal[0], red[0]);
}

__global__ void k_prep(const float* __restrict__ We1, const float* __restrict__ ae1,
                       const float* __restrict__ We2, const float* __restrict__ ae2, int E) {
    int t = threadIdx.x;
    if (t == 0) g_scal[1] = g_scal[0] / (float)E;
    if (t < 4) {
        int layer = t >> 1, hh = t & 1;
        const float* We = layer ? We2 : We1;
        const float* ae = layer ? ae2 : ae1;
        float c = 0.f;
        for (int i = 0; i < 16; i++) c += We[hh * 16 + i] * ae[hh * 16 + i];
        g_scal[2 + layer * 2 + hh] = c;
    }
}

// ---------------------------------------------------------------------------
__global__ void k_scan1(int n) {
    __shared__ int sm[1024];
    int t = threadIdx.x;
    int i = blockIdx.x * 1024 + t;
    int v = (i < n) ? g_deg[i] : 0;
    int x = v;
    sm[t] = x;
    __syncthreads();
    #pragma unroll
    for (int off = 1; off < 1024; off <<= 1) {
        int y = (t >= off) ? sm[t - off] : 0;
        __syncthreads();
        x += y;
        sm[t] = x;
        __syncthreads();
    }
    if (i < n) g_rowptr[i] = x - v;   // exclusive, pre-offset
    if (t == 1023) g_bsum[blockIdx.x] = x;
}

__global__ void k_scan2(int nb) {
    __shared__ int sm[1024];
    int t = threadIdx.x;
    int v = (t < nb) ? g_bsum[t] : 0;
    int x = v;
    sm[t] = x;
    __syncthreads();
    #pragma unroll
    for (int off = 1; off < 1024; off <<= 1) {
        int y = (t >= off) ? sm[t - off] : 0;
        __syncthreads();
        x += y;
        sm[t] = x;
        __syncthreads();
    }
    if (t < nb) g_boff[t] = x - v;    // exclusive
}

__global__ void k_scan3(int n, int E) {
    int i = blockIdx.x * blockDim.x + threadIdx.x;
    if (i < n)
        g_rowptr[i] += g_boff[i >> 10];
    if (i == 0) g_rowptr[n] = E;
}

// atomic-free scatter: slot = rowptr[dst] + rank[e]
__global__ void k_scatter(const int* __restrict__ ei, const float* __restrict__ ea,
                          int E, int n) {
    for (int e = blockIdx.x * blockDim.x + threadIdx.x; e < E; e += gridDim.x * blockDim.x) {
        int s = clampi(ei[e], n);
        int d = clampi(ei[E + e], n);
        g_csr[g_rowptr[d] + g_rank[e]] = make_int2(s, __float_as_int(ea[e]));
    }
}

// ---------------------------------------------------------------------------
// layer-1 transform: h = x @ W1; emits asrc/adst.
__global__ void k_transform1(const float* __restrict__ xin,
                             const float* __restrict__ W,
                             const float* __restrict__ a_src,
                             const float* __restrict__ a_dst, int n) {
    constexpr int FIN = 128;
    __shared__ float W_sh[FIN * 32];
    __shared__ float x_sh[32][FIN + 1];
    __shared__ float s_as[32], s_ad[32];
    __shared__ float sm_ps[8][32], sm_pd[8][32];
    int tid = threadIdx.x;
    for (int i = tid; i < FIN * 32; i += 256) W_sh[i] = W[i];
    if (tid < 32) {
        s_as[tid] = a_src[tid];
        s_ad[tid] = a_dst[tid];
    }
    __syncthreads();
    int nb = blockIdx.x * 32;
    for (int i = tid; i < 32 * FIN; i += 256) {
        int r = i / FIN, c = i % FIN;
        int node = nb + r;
        x_sh[r][c] = (node < n) ? xin[(size_t)node * FIN + c] : 0.f;
    }
    __syncthreads();

    int w = tid >> 5, lane = tid & 31;
    int node = nb + lane;
    float4 acc = make_float4(0.f, 0.f, 0.f, 0.f);
    const float4* W4 = (const float4*)W_sh;
    #pragma unroll 8
    for (int k = 0; k < FIN; k++) {
        float4 wv = W4[k * 8 + w];     // same addr across warp -> broadcast
        float xv = x_sh[lane][k];      // conflict-free (stride FIN+1)
        acc.x = fmaf(xv, wv.x, acc.x);
        acc.y = fmaf(xv, wv.y, acc.y);
        acc.z = fmaf(xv, wv.z, acc.z);
        acc.w = fmaf(xv, wv.w, acc.w);
    }
    if (node < n)
        ((float4*)(g_h + node * 32))[w] = acc;

    sm_ps[w][lane] = acc.x * s_as[w * 4]     + acc.y * s_as[w * 4 + 1]
                   + acc.z * s_as[w * 4 + 2] + acc.w * s_as[w * 4 + 3];
    sm_pd[w][lane] = acc.x * s_ad[w * 4]     + acc.y * s_ad[w * 4 + 1]
                   + acc.z * s_ad[w * 4 + 2] + acc.w * s_ad[w * 4 + 3];
    __syncthreads();
    if (tid < 64) {
        int l = tid & 31, hh = tid >> 5;
        int node2 = nb + l;
        if (node2 < n) {
            int wb = hh * 4;
            float vs = sm_ps[wb][l] + sm_ps[wb + 1][l] + sm_ps[wb + 2][l] + sm_ps[wb + 3][l];
            float vd = sm_pd[wb][l] + sm_pd[wb + 1][l] + sm_pd[wb + 2][l] + sm_pd[wb + 3][l];
            g_asrc[node2 * 2 + hh] = vs;
            g_adst[node2 * 2 + hh] = vd;
        }
    }
}

// ---------------------------------------------------------------------------
// fused aggregation: warp per dst node; 4 edges per gather iteration
// (four 8-lane groups, float4 column quads per lane).
// LAYER==0: features g_h/asrc/adst; epilogue = layer-2 transform -> g_out.
// LAYER==1: features g_out/asrc2/adst2; epilogue = mean-pool accumulation.
template <int LAYER>
__global__ void __launch_bounds__(256, 6)
k_agg(int n,
      const float* __restrict__ W2, const float* __restrict__ b1,
      const float* __restrict__ as2, const float* __restrict__ ad2,
      const int* __restrict__ batch, const float* __restrict__ b2,
      int G) {
    __shared__ float4 stage[8][32];
    __shared__ float W2s[32 * 32];
    __shared__ float b1s[32], as2s[32], ad2s[32];
    int tid = threadIdx.x;
    if (LAYER == 0) {
        for (int i = tid; i < 1024; i += 256) W2s[i] = W2[i];
        if (tid < 32) {
            b1s[tid] = b1[tid];
            as2s[tid] = as2[tid];
            ad2s[tid] = ad2[tid];
        }
        __syncthreads();
    }

    int wg = (blockIdx.x * blockDim.x + tid) >> 5;
    if (wg >= n) return;
    int w = tid >> 5, lane = tid & 31;
    int grp = lane >> 3;           // 4 groups of 8 lanes; group g takes edge t+g
    int q = lane & 7;              // lane-in-group owns columns 4q..4q+3
    int node = wg;
    float c0 = g_scal[2 + LAYER * 2];
    float c1 = g_scal[3 + LAYER * 2];
    float mean = g_scal[1];
    const float*  hf   = LAYER ? g_out   : g_h;
    const float4* hf4  = (const float4*)hf;
    const float*  asrc = LAYER ? g_asrc2 : g_asrc;
    const float*  adst = LAYER ? g_adst2 : g_adst;
    float2 ad = ((const float2*)adst)[node];
    bool head1 = q >= 4;           // column quad's head (cols 16..31 -> head 1)

    float4 acc = make_float4(0.f, 0.f, 0.f, 0.f);
    float s0 = 0.f, s1 = 0.f;
    int beg = g_rowptr[node], end = g_rowptr[node + 1];

    for (int j0 = beg; j0 < end; j0 += 32) {
        int j = j0 + lane;
        bool v = j < end;
        int src = node;
        float av = 0.f;
        if (v) {
            int2 p = g_csr[j];
            src = p.x;
            av = __int_as_float(p.y);
        }
        float2 as = ((const float2*)asrc)[src];
        float a0 = as.x + ad.x + av * c0;
        float a1 = as.y + ad.y + av * c1;
        a0 = a0 > 0.f ? a0 : 0.2f * a0;
        a1 = a1 > 0.f ? a1 : 0.2f * a1;
        float ex0 = v ? __expf(a0) : 0.f;   // invalid lanes stage ex=0
        float ex1 = v ? __expf(a1) : 0.f;
        s0 += ex0;
        s1 += ex1;
        stage[w][lane] = make_float4(__int_as_float(src), ex0, ex1, 0.f);
        __syncwarp();
        int cnt = min(end - j0, 32);
        if (cnt == 32) {
            #pragma unroll
            for (int t = 0; t < 32; t += 4) {
                float4 p = stage[w][t + grp];             // 4 consecutive f4 slots
                float4 hv = hf4[__float_as_int(p.x) * 8 + q];   // LDG.128, 1 line/edge
                float e = head1 ? p.z : p.y;
                acc.x = fmaf(hv.x, e, acc.x);
                acc.y = fmaf(hv.y, e, acc.y);
                acc.z = fmaf(hv.z, e, acc.z);
                acc.w = fmaf(hv.w, e, acc.w);
            }
        } else {
            for (int t = 0; t < cnt; t += 4) {            // slots >= cnt carry ex=0
                float4 p = stage[w][t + grp];
                float4 hv = hf4[__float_as_int(p.x) * 8 + q];
                float e = head1 ? p.z : p.y;
                acc.x = fmaf(hv.x, e, acc.x);
                acc.y = fmaf(hv.y, e, acc.y);
                acc.z = fmaf(hv.z, e, acc.z);
                acc.w = fmaf(hv.w, e, acc.w);
            }
        }
        __syncwarp();
    }

    // combine the 4 groups (lanes q, q+8, q+16, q+24 hold the same columns)
    acc.x += __shfl_down_sync(0xffffffffu, acc.x, 16);
    acc.y += __shfl_down_sync(0xffffffffu, acc.y, 16);
    acc.z += __shfl_down_sync(0xffffffffu, acc.z, 16);
    acc.w += __shfl_down_sync(0xffffffffu, acc.w, 16);
    acc.x += __shfl_down_sync(0xffffffffu, acc.x, 8);
    acc.y += __shfl_down_sync(0xffffffffu, acc.y, 8);
    acc.z += __shfl_down_sync(0xffffffffu, acc.z, 8);
    acc.w += __shfl_down_sync(0xffffffffu, acc.w, 8);

    // self loop (src = node, ea = mean): add in lanes 0-7 after combine
    {
        float2 as = ((const float2*)asrc)[node];
        float a0 = as.x + ad.x + mean * c0;
        float a1 = as.y + ad.y + mean * c1;
        a0 = a0 > 0.f ? a0 : 0.2f * a0;
        a1 = a1 > 0.f ? a1 : 0.2f * a1;
        float ex0 = __expf(a0), ex1 = __expf(a1);
        if (lane == 0) { s0 += ex0; s1 += ex1; }
        float4 hv = hf4[node * 8 + q];
        float e = (lane < 8) ? (head1 ? ex1 : ex0) : 0.f;
        acc.x = fmaf(hv.x, e, acc.x);
        acc.y = fmaf(hv.y, e, acc.y);
        acc.z = fmaf(hv.z, e, acc.z);
        acc.w = fmaf(hv.w, e, acc.w);
    }

    #pragma unroll
    for (int off = 16; off; off >>= 1) {
        s0 += __shfl_xor_sync(0xffffffffu, s0, off);
        s1 += __shfl_xor_sync(0xffffffffu, s1, off);
    }
    float sinv = 1.f / ((head1 ? s1 : s0) + 1e-16f);
    float4 o4 = make_float4(acc.x * sinv, acc.y * sinv, acc.z * sinv, acc.w * sinv);
    // o4 valid in lanes 0-7 (columns 4q..4q+3)

    if (LAYER == 0) {
        // fused layer-2 transform: x2 = relu(o + b1); h2 = x2 @ W2
        float* xrow = (float*)&stage[w][0];
        if (lane < 8) {
            xrow[4 * q]     = fmaxf(o4.x + b1s[4 * q], 0.f);
            xrow[4 * q + 1] = fmaxf(o4.y + b1s[4 * q + 1], 0.f);
            xrow[4 * q + 2] = fmaxf(o4.z + b1s[4 * q + 2], 0.f);
            xrow[4 * q + 3] = fmaxf(o4.w + b1s[4 * q + 3], 0.f);
        }
        __syncwarp();
        float acc2 = 0.f;
        #pragma unroll 8
        for (int k = 0; k < 32; k++)
            acc2 = fmaf(xrow[k], W2s[k * 32 + lane], acc2);
        g_out[node * 32 + lane] = acc2;
        float ps = acc2 * as2s[lane];
        float pd = acc2 * ad2s[lane];
        #pragma unroll
        for (int off = 8; off; off >>= 1) {
            ps += __shfl_down_sync(0xffffffffu, ps, off, 16);
            pd += __shfl_down_sync(0xffffffffu, pd, off, 16);
        }
        if ((lane & 15) == 0) {
            int hh = lane >> 4;
            g_asrc2[node * 2 + hh] = ps;
            g_adst2[node * 2 + hh] = pd;
        }
    } else {
        int g = clampi(batch[node], G);
        if (lane < 8) {
            float4 add = make_float4(o4.x + b2[4 * q],     o4.y + b2[4 * q + 1],
                                     o4.z + b2[4 * q + 2], o4.w + b2[4 * q + 3]);
            atomicAdd((float4*)&g_pool[g * 32 + 4 * q], add);
        }
        if (lane == 0) atomicAdd(&g_cnt[g], 1.f);
    }
}

// ---------------------------------------------------------------------------
__global__ void k_mlp(float* __restrict__ out,
                      const float* __restrict__ Wf1, const float* __restrict__ bf1,
                      const float* __restrict__ Wf2, const float* __restrict__ bf2, int G) {
    int g = blockIdx.x * blockDim.x + threadIdx.x;
    if (g >= G) return;
    float inv = 1.f / fmaxf(g_cnt[g], 1.f);
    float emb[32];
    #pragma unroll
    for (int i = 0; i < 32; i++) emb[i] = g_pool[g * 32 + i] * inv;
    float o0 = bf2[0], o1 = bf2[1];
    for (int j = 0; j < 32; j++) {
        float z = bf1[j];
        #pragma unroll
        for (int i = 0; i < 32; i++) z = fmaf(emb[i], Wf1[i * 32 + j], z);
        z = fmaxf(z, 0.f);
        o0 = fmaf(z, Wf2[j * 2], o0);
        o1 = fmaf(z, Wf2[j * 2 + 1], o1);
    }
    out[g * 2] = o0;
    out[g * 2 + 1] = o1;
}

// ---------------------------------------------------------------------------
extern "C" void kernel_launch(void* const* d_in, const int* in_sizes, int n_in,
                              void* d_out, int out_size) {
    const float* x     = (const float*)d_in[0];
    const int*   ei    = (const int*)d_in[1];
    const float* ea    = (const float*)d_in[2];
    const int*   batch = (const int*)d_in[3];
    const float* W1  = (const float*)d_in[4];
    const float* as1 = (const float*)d_in[5];
    const float* ad1 = (const float*)d_in[6];
    const float* We1 = (const float*)d_in[7];
    const float* ae1 = (const float*)d_in[8];
    const float* b1  = (const float*)d_in[9];
    const float* W2  = (const float*)d_in[10];
    const float* as2 = (const float*)d_in[11];
    const float* ad2 = (const float*)d_in[12];
    const float* We2 = (const float*)d_in[13];
    const float* ae2 = (const float*)d_in[14];
    const float* b2  = (const float*)d_in[15];
    const float* Wf1 = (const float*)d_in[16];
    const float* bf1 = (const float*)d_in[17];
    const float* Wf2 = (const float*)d_in[18];
    const float* bf2 = (const float*)d_in[19];

    int N = in_sizes[0] / 128;
    int E = in_sizes[1] / 2;
    int G = out_size / 2;
    int nb = (N + 1023) / 1024;
    int tb = (N + 31) / 32;
    int ab = (N + 7) / 8;

    k_init<<<128, 1024>>>(N);
    k_hist<<<2048, 256>>>(ei, ea, E, N);
    k_prep<<<1, 32>>>(We1, ae1, We2, ae2, E);

    k_scan1<<<nb, 1024>>>(N);
    k_scan2<<<1, 1024>>>(nb);
    k_scan3<<<(N + 1023) / 1024, 1024>>>(N, E);
    k_scatter<<<2048, 512>>>(ei, ea, E, N);

    // layer 1 transform, then agg0 (with fused layer-2 transform epilogue)
    k_transform1<<<tb, 256>>>(x, W1, as1, ad1, N);
    k_agg<0><<<ab, 256>>>(N, W2, b1, as2, ad2, nullptr, nullptr, G);

    // layer 2 aggregation with fused mean-pool
    k_agg<1><<<ab, 256>>>(N, nullptr, nullptr, nullptr, nullptr, batch, b2, G);

    k_mlp<<<1, 64>>>((float*)d_out, Wf1, bf1, Wf2, bf2, G);
}

// round 11
// speedup vs baseline: 1.0681x; 1.0108x over previous
#include <cuda_runtime.h>
#include <cuda_fp16.h>

// ---------------------------------------------------------------------------
// GAT (2 layers, edge features, H=2 heads x C=16) + mean pool + MLP -> [G,2]
// dst-CSR built once; atomic-free warp-per-node aggregation, 4 edges per
// gather iteration (8-lane groups, 4 cols each); feature rows stored fp16
// (64B/node) to halve gather L2 traffic; layer-2 transform fused into agg0
// epilogue; pool fused into agg1. All reductions/attention math in fp32.
// ---------------------------------------------------------------------------

#define MAXN 100352
#define MAXE 3211264
#define MAXG 256
#define NBS ((MAXN + 1023) / 1024)

__device__ __align__(16) uint2 g_h[MAXN * 8];       // layer-1 features, fp16x4 per uint2
__device__ __align__(16) uint2 g_out[MAXN * 8];     // layer-2 features, fp16x4 per uint2
__device__ __align__(16) float g_asrc[MAXN * 2];
__device__ __align__(16) float g_adst[MAXN * 2];
__device__ __align__(16) float g_asrc2[MAXN * 2];
__device__ __align__(16) float g_adst2[MAXN * 2];
__device__ __align__(16) int2  g_csr[MAXE];         // (src, ea_bits), dst-sorted
__device__ int g_rank[MAXE];
__device__ int g_rowptr[MAXN + 1];
__device__ int g_deg[MAXN];
__device__ int g_bsum[NBS];
__device__ int g_boff[NBS];
__device__ __align__(16) float g_scal[8];           // [0]=esum [1]=mean [2..5]=ce
__device__ __align__(16) float g_pool[MAXG * 32];
__device__ float g_cnt[MAXG];

__device__ __forceinline__ int clampi(int v, int hi) {
    return v < 0 ? 0 : (v >= hi ? hi - 1 : v);
}

// ---------------------------------------------------------------------------
__global__ void k_init(int n) {
    int stride = gridDim.x * blockDim.x;
    for (int i = blockIdx.x * blockDim.x + threadIdx.x; i < n; i += stride)
        g_deg[i] = 0;
    int t = blockIdx.x * blockDim.x + threadIdx.x;
    if (t < 8) g_scal[t] = 0.f;
    if (t < MAXG) g_cnt[t] = 0.f;
    if (t < MAXG * 32) g_pool[t] = 0.f;
}

// histogram (captures per-edge rank) + edge_attr sum in one pass
__global__ void k_hist(const int* __restrict__ ei, const float* __restrict__ ea,
                       int E, int n) {
    __shared__ float red[256];
    float acc = 0.f;
    for (int e = blockIdx.x * 256 + threadIdx.x; e < E; e += gridDim.x * 256) {
        int d = clampi(ei[E + e], n);
        g_rank[e] = atomicAdd(&g_deg[d], 1);
        acc += ea[e];
    }
    red[threadIdx.x] = acc;
    __syncthreads();
    for (int s = 128; s; s >>= 1) {
        if (threadIdx.x < s) red[threadIdx.x] += red[threadIdx.x + s];
        __syncthreads();
    }
    if (threadIdx.x == 0) atomicAdd(&g_scal[0], red[0]);
}

__global__ void k_prep(const float* __restrict__ We1, const float* __restrict__ ae1,
                       const float* __restrict__ We2, const float* __restrict__ ae2, int E) {
    int t = threadIdx.x;
    if (t == 0) g_scal[1] = g_scal[0] / (float)E;
    if (t < 4) {
        int layer = t >> 1, hh = t & 1;
        const float* We = layer ? We2 : We1;
        const float* ae = layer ? ae2 : ae1;
        float c = 0.f;
        for (int i = 0; i < 16; i++) c += We[hh * 16 + i] * ae[hh * 16 + i];
        g_scal[2 + layer * 2 + hh] = c;
    }
}

// ---------------------------------------------------------------------------
__global__ void k_scan1(int n) {
    __shared__ int sm[1024];
    int t = threadIdx.x;
    int i = blockIdx.x * 1024 + t;
    int v = (i < n) ? g_deg[i] : 0;
    int x = v;
    sm[t] = x;
    __syncthreads();
    #pragma unroll
    for (int off = 1; off < 1024; off <<= 1) {
        int y = (t >= off) ? sm[t - off] : 0;
        __syncthreads();
        x += y;
        sm[t] = x;
        __syncthreads();
    }
    if (i < n) g_rowptr[i] = x - v;   // exclusive, pre-offset
    if (t == 1023) g_bsum[blockIdx.x] = x;
}

__global__ void k_scan2(int nb) {
    __shared__ int sm[1024];
    int t = threadIdx.x;
    int v = (t < nb) ? g_bsum[t] : 0;
    int x = v;
    sm[t] = x;
    __syncthreads();
    #pragma unroll
    for (int off = 1; off < 1024; off <<= 1) {
        int y = (t >= off) ? sm[t - off] : 0;
        __syncthreads();
        x += y;
        sm[t] = x;
        __syncthreads();
    }
    if (t < nb) g_boff[t] = x - v;    // exclusive
}

__global__ void k_scan3(int n, int E) {
    int i = blockIdx.x * blockDim.x + threadIdx.x;
    if (i < n)
        g_rowptr[i] += g_boff[i >> 10];
    if (i == 0) g_rowptr[n] = E;
}

// atomic-free scatter: slot = rowptr[dst] + rank[e]
__global__ void k_scatter(const int* __restrict__ ei, const float* __restrict__ ea,
                          int E, int n) {
    for (int e = blockIdx.x * blockDim.x + threadIdx.x; e < E; e += gridDim.x * blockDim.x) {
        int s = clampi(ei[e], n);
        int d = clampi(ei[E + e], n);
        g_csr[g_rowptr[d] + g_rank[e]] = make_int2(s, __float_as_int(ea[e]));
    }
}

// ---------------------------------------------------------------------------
// layer-1 transform: h = x @ W1 (stored fp16); emits asrc/adst (fp32).
__global__ void k_transform1(const float* __restrict__ xin,
                             const float* __restrict__ W,
                             const float* __restrict__ a_src,
                             const float* __restrict__ a_dst, int n) {
    constexpr int FIN = 128;
    __shared__ float W_sh[FIN * 32];
    __shared__ float x_sh[32][FIN + 1];
    __shared__ float s_as[32], s_ad[32];
    __shared__ float sm_ps[8][32], sm_pd[8][32];
    int tid = threadIdx.x;
    for (int i = tid; i < FIN * 32; i += 256) W_sh[i] = W[i];
    if (tid < 32) {
        s_as[tid] = a_src[tid];
        s_ad[tid] = a_dst[tid];
    }
    __syncthreads();
    int nb = blockIdx.x * 32;
    for (int i = tid; i < 32 * FIN; i += 256) {
        int r = i / FIN, c = i % FIN;
        int node = nb + r;
        x_sh[r][c] = (node < n) ? xin[(size_t)node * FIN + c] : 0.f;
    }
    __syncthreads();

    int w = tid >> 5, lane = tid & 31;
    int node = nb + lane;
    float4 acc = make_float4(0.f, 0.f, 0.f, 0.f);
    const float4* W4 = (const float4*)W_sh;
    #pragma unroll 8
    for (int k = 0; k < FIN; k++) {
        float4 wv = W4[k * 8 + w];     // same addr across warp -> broadcast
        float xv = x_sh[lane][k];      // conflict-free (stride FIN+1)
        acc.x = fmaf(xv, wv.x, acc.x);
        acc.y = fmaf(xv, wv.y, acc.y);
        acc.z = fmaf(xv, wv.z, acc.z);
        acc.w = fmaf(xv, wv.w, acc.w);
    }
    if (node < n) {
        union { __half2 h[2]; uint2 u; } pk;
        pk.h[0] = __floats2half2_rn(acc.x, acc.y);
        pk.h[1] = __floats2half2_rn(acc.z, acc.w);
        g_h[node * 8 + w] = pk.u;
    }

    sm_ps[w][lane] = acc.x * s_as[w * 4]     + acc.y * s_as[w * 4 + 1]
                   + acc.z * s_as[w * 4 + 2] + acc.w * s_as[w * 4 + 3];
    sm_pd[w][lane] = acc.x * s_ad[w * 4]     + acc.y * s_ad[w * 4 + 1]
                   + acc.z * s_ad[w * 4 + 2] + acc.w * s_ad[w * 4 + 3];
    __syncthreads();
    if (tid < 64) {
        int l = tid & 31, hh = tid >> 5;
        int node2 = nb + l;
        if (node2 < n) {
            int wb = hh * 4;
            float vs = sm_ps[wb][l] + sm_ps[wb + 1][l] + sm_ps[wb + 2][l] + sm_ps[wb + 3][l];
            float vd = sm_pd[wb][l] + sm_pd[wb + 1][l] + sm_pd[wb + 2][l] + sm_pd[wb + 3][l];
            g_asrc[node2 * 2 + hh] = vs;
            g_adst[node2 * 2 + hh] = vd;
        }
    }
}

// ---------------------------------------------------------------------------
// fused aggregation: warp per dst node; 4 edges per gather iteration
// (four 8-lane groups); fp16 feature rows decoded to fp32 for accumulation.
// LAYER==0: features g_h/asrc/adst; epilogue = layer-2 transform -> g_out.
// LAYER==1: features g_out/asrc2/adst2; epilogue = mean-pool accumulation.
template <int LAYER>
__global__ void __launch_bounds__(256, 6)
k_agg(int n,
      const float* __restrict__ W2, const float* __restrict__ b1,
      const float* __restrict__ as2, const float* __restrict__ ad2,
      const int* __restrict__ batch, const float* __restrict__ b2,
      int G) {
    __shared__ float4 stage[8][32];
    __shared__ float W2s[32 * 32];
    __shared__ float b1s[32], as2s[32], ad2s[32];
    int tid = threadIdx.x;
    if (LAYER == 0) {
        for (int i = tid; i < 1024; i += 256) W2s[i] = W2[i];
        if (tid < 32) {
            b1s[tid] = b1[tid];
            as2s[tid] = as2[tid];
            ad2s[tid] = ad2[tid];
        }
        __syncthreads();
    }

    int wg = (blockIdx.x * blockDim.x + tid) >> 5;
    if (wg >= n) return;
    int w = tid >> 5, lane = tid & 31;
    int grp = lane >> 3;           // 4 groups of 8 lanes; group g takes edge t+g
    int q = lane & 7;              // lane-in-group owns columns 4q..4q+3
    int node = wg;
    float c0 = g_scal[2 + LAYER * 2];
    float c1 = g_scal[3 + LAYER * 2];
    float mean = g_scal[1];
    const uint2*  hf8  = LAYER ? g_out   : g_h;
    const float*  asrc = LAYER ? g_asrc2 : g_asrc;
    const float*  adst = LAYER ? g_adst2 : g_adst;
    float2 ad = ((const float2*)adst)[node];
    bool head1 = q >= 4;           // column quad's head (cols 16..31 -> head 1)

    float4 acc = make_float4(0.f, 0.f, 0.f, 0.f);
    float s0 = 0.f, s1 = 0.f;
    int beg = g_rowptr[node], end = g_rowptr[node + 1];

    for (int j0 = beg; j0 < end; j0 += 32) {
        int j = j0 + lane;
        bool v = j < end;
        int src = node;
        float av = 0.f;
        if (v) {
            int2 p = g_csr[j];
            src = p.x;
            av = __int_as_float(p.y);
        }
        float2 as = ((const float2*)asrc)[src];
        float a0 = as.x + ad.x + av * c0;
        float a1 = as.y + ad.y + av * c1;
        a0 = a0 > 0.f ? a0 : 0.2f * a0;
        a1 = a1 > 0.f ? a1 : 0.2f * a1;
        float ex0 = v ? __expf(a0) : 0.f;   // invalid lanes stage ex=0
        float ex1 = v ? __expf(a1) : 0.f;
        s0 += ex0;
        s1 += ex1;
        stage[w][lane] = make_float4(__int_as_float(src), ex0, ex1, 0.f);
        __syncwarp();
        int cnt = min(end - j0, 32);
        if (cnt == 32) {
            #pragma unroll
            for (int t = 0; t < 32; t += 4) {
                float4 p = stage[w][t + grp];
                union { uint2 u; __half2 h[2]; } pk;
                pk.u = hf8[__float_as_int(p.x) * 8 + q];   // LDG.64, 64B row/edge
                float2 f01 = __half22float2(pk.h[0]);
                float2 f23 = __half22float2(pk.h[1]);
                float e = head1 ? p.z : p.y;
                acc.x = fmaf(f01.x, e, acc.x);
                acc.y = fmaf(f01.y, e, acc.y);
                acc.z = fmaf(f23.x, e, acc.z);
                acc.w = fmaf(f23.y, e, acc.w);
            }
        } else {
            for (int t = 0; t < cnt; t += 4) {            // slots >= cnt carry ex=0
                float4 p = stage[w][t + grp];
                union { uint2 u; __half2 h[2]; } pk;
                pk.u = hf8[__float_as_int(p.x) * 8 + q];
                float2 f01 = __half22float2(pk.h[0]);
                float2 f23 = __half22float2(pk.h[1]);
                float e = head1 ? p.z : p.y;
                acc.x = fmaf(f01.x, e, acc.x);
                acc.y = fmaf(f01.y, e, acc.y);
                acc.z = fmaf(f23.x, e, acc.z);
                acc.w = fmaf(f23.y, e, acc.w);
            }
        }
        __syncwarp();
    }

    // combine the 4 groups (lanes q, q+8, q+16, q+24 hold the same columns)
    acc.x += __shfl_down_sync(0xffffffffu, acc.x, 16);
    acc.y += __shfl_down_sync(0xffffffffu, acc.y, 16);
    acc.z += __shfl_down_sync(0xffffffffu, acc.z, 16);
    acc.w += __shfl_down_sync(0xffffffffu, acc.w, 16);
    acc.x += __shfl_down_sync(0xffffffffu, acc.x, 8);
    acc.y += __shfl_down_sync(0xffffffffu, acc.y, 8);
    acc.z += __shfl_down_sync(0xffffffffu, acc.z, 8);
    acc.w += __shfl_down_sync(0xffffffffu, acc.w, 8);

    // self loop (src = node, ea = mean): add in lanes 0-7 after combine
    {
        float2 as = ((const float2*)asrc)[node];
        float a0 = as.x + ad.x + mean * c0;
        float a1 = as.y + ad.y + mean * c1;
        a0 = a0 > 0.f ? a0 : 0.2f * a0;
        a1 = a1 > 0.f ? a1 : 0.2f * a1;
        float ex0 = __expf(a0), ex1 = __expf(a1);
        if (lane == 0) { s0 += ex0; s1 += ex1; }
        union { uint2 u; __half2 h[2]; } pk;
        pk.u = hf8[node * 8 + q];
        float2 f01 = __half22float2(pk.h[0]);
        float2 f23 = __half22float2(pk.h[1]);
        float e = (lane < 8) ? (head1 ? ex1 : ex0) : 0.f;
        acc.x = fmaf(f01.x, e, acc.x);
        acc.y = fmaf(f01.y, e, acc.y);
        acc.z = fmaf(f23.x, e, acc.z);
        acc.w = fmaf(f23.y, e, acc.w);
    }

    #pragma unroll
    for (int off = 16; off; off >>= 1) {
        s0 += __shfl_xor_sync(0xffffffffu, s0, off);
        s1 += __shfl_xor_sync(0xffffffffu, s1, off);
    }
    float sinv = 1.f / ((head1 ? s1 : s0) + 1e-16f);
    float4 o4 = make_float4(acc.x * sinv, acc.y * sinv, acc.z * sinv, acc.w * sinv);
    // o4 valid in lanes 0-7 (columns 4q..4q+3)

    if (LAYER == 0) {
        // fused layer-2 transform: x2 = relu(o + b1); h2 = x2 @ W2 (fp32 math)
        float* xrow = (float*)&stage[w][0];
        if (lane < 8) {
            xrow[4 * q]     = fmaxf(o4.x + b1s[4 * q], 0.f);
            xrow[4 * q + 1] = fmaxf(o4.y + b1s[4 * q + 1], 0.f);
            xrow[4 * q + 2] = fmaxf(o4.z + b1s[4 * q + 2], 0.f);
            xrow[4 * q + 3] = fmaxf(o4.w + b1s[4 * q + 3], 0.f);
        }
        __syncwarp();
        float acc2 = 0.f;
        #pragma unroll 8
        for (int k = 0; k < 32; k++)
            acc2 = fmaf(xrow[k], W2s[k * 32 + lane], acc2);
        // store h2 row as fp16 (pairs from even lanes)
        float nbv = __shfl_down_sync(0xffffffffu, acc2, 1);
        if ((lane & 1) == 0) {
            __half2 hv = __floats2half2_rn(acc2, nbv);
            ((unsigned*)g_out)[node * 16 + (lane >> 1)] = *(unsigned*)&hv;
        }
        float ps = acc2 * as2s[lane];
        float pd = acc2 * ad2s[lane];
        #pragma unroll
        for (int off = 8; off; off >>= 1) {
            ps += __shfl_down_sync(0xffffffffu, ps, off, 16);
            pd += __shfl_down_sync(0xffffffffu, pd, off, 16);
        }
        if ((lane & 15) == 0) {
            int hh = lane >> 4;
            g_asrc2[node * 2 + hh] = ps;
            g_adst2[node * 2 + hh] = pd;
        }
    } else {
        int g = clampi(batch[node], G);
        if (lane < 8) {
            float4 add = make_float4(o4.x + b2[4 * q],     o4.y + b2[4 * q + 1],
                                     o4.z + b2[4 * q + 2], o4.w + b2[4 * q + 3]);
            atomicAdd((float4*)&g_pool[g * 32 + 4 * q], add);
        }
        if (lane == 0) atomicAdd(&g_cnt[g], 1.f);
    }
}

// ---------------------------------------------------------------------------
__global__ void k_mlp(float* __restrict__ out,
                      const float* __restrict__ Wf1, const float* __restrict__ bf1,
                      const float* __restrict__ Wf2, const float* __restrict__ bf2, int G) {
    int g = blockIdx.x * blockDim.x + threadIdx.x;
    if (g >= G) return;
    float inv = 1.f / fmaxf(g_cnt[g], 1.f);
    float emb[32];
    #pragma unroll
    for (int i = 0; i < 32; i++) emb[i] = g_pool[g * 32 + i] * inv;
    float o0 = bf2[0], o1 = bf2[1];
    for (int j = 0; j < 32; j++) {
        float z = bf1[j];
        #pragma unroll
        for (int i = 0; i < 32; i++) z = fmaf(emb[i], Wf1[i * 32 + j], z);
        z = fmaxf(z, 0.f);
        o0 = fmaf(z, Wf2[j * 2], o0);
        o1 = fmaf(z, Wf2[j * 2 + 1], o1);
    }
    out[g * 2] = o0;
    out[g * 2 + 1] = o1;
}

// ---------------------------------------------------------------------------
extern "C" void kernel_launch(void* const* d_in, const int* in_sizes, int n_in,
                              void* d_out, int out_size) {
    const float* x     = (const float*)d_in[0];
    const int*   ei    = (const int*)d_in[1];
    const float* ea    = (const float*)d_in[2];
    const int*   batch = (const int*)d_in[3];
    const float* W1  = (const float*)d_in[4];
    const float* as1 = (const float*)d_in[5];
    const float* ad1 = (const float*)d_in[6];
    const float* We1 = (const float*)d_in[7];
    const float* ae1 = (const float*)d_in[8];
    const float* b1  = (const float*)d_in[9];
    const float* W2  = (const float*)d_in[10];
    const float* as2 = (const float*)d_in[11];
    const float* ad2 = (const float*)d_in[12];
    const float* We2 = (const float*)d_in[13];
    const float* ae2 = (const float*)d_in[14];
    const float* b2  = (const float*)d_in[15];
    const float* Wf1 = (const float*)d_in[16];
    const float* bf1 = (const float*)d_in[17];
    const float* Wf2 = (const float*)d_in[18];
    const float* bf2 = (const float*)d_in[19];

    int N = in_sizes[0] / 128;
    int E = in_sizes[1] / 2;
    int G = out_size / 2;
    int nb = (N + 1023) / 1024;
    int tb = (N + 31) / 32;
    int ab = (N + 7) / 8;

    k_init<<<128, 1024>>>(N);
    k_hist<<<2048, 256>>>(ei, ea, E, N);
    k_prep<<<1, 32>>>(We1, ae1, We2, ae2, E);

    k_scan1<<<nb, 1024>>>(N);
    k_scan2<<<1, 1024>>>(nb);
    k_scan3<<<(N + 1023) / 1024, 1024>>>(N, E);
    k_scatter<<<2048, 512>>>(ei, ea, E, N);

    // layer 1 transform, then agg0 (with fused layer-2 transform epilogue)
    k_transform1<<<tb, 256>>>(x, W1, as1, ad1, N);
    k_agg<0><<<ab, 256>>>(N, W2, b1, as2, ad2, nullptr, nullptr, G);

    // layer 2 aggregation with fused mean-pool
    k_agg<1><<<ab, 256>>>(N, nullptr, nullptr, nullptr, nullptr, batch, b2, G);

    k_mlp<<<1, 64>>>((float*)d_out, Wf1, bf1, Wf2, bf2, G);
}